// round 4
// baseline (speedup 1.0000x reference)
#include <cuda_runtime.h>
#include <math.h>

#define NP 4096
#define NBLK 256
#define NEG_LOGN (-8.317766166719343f)   /* -log(4096) */

struct __align__(16) Scratch {
    float C[(size_t)NP * NP];      // 64 MB cost matrix (reused per phase)
    float xt[NP * 64], yt[NP * 64];
    float sqx[NP], sqy[NP];
    float f[2][NP], g[2][NP];      // ping-pong potentials
    float fin[4][NP];              // faa_f, gbb_f, fba_f, gab_f
    float pm[32 * NP], ps[32 * NP];// column-LSE partials (max, sum)
};
__device__ Scratch S;

// ---------------------------------------------------------------------------
// software grid barrier (all NBLK blocks co-resident by construction)
// ---------------------------------------------------------------------------
__device__ unsigned g_cnt;
__device__ unsigned g_gen;

__device__ __forceinline__ void gsync() {
    __threadfence();
    __syncthreads();
    if (threadIdx.x == 0) {
        volatile unsigned* vg = &g_gen;
        unsigned my = *vg;
        if (atomicAdd(&g_cnt, 1u) == NBLK - 1u) {
            g_cnt = 0u;
            __threadfence();
            *vg = my + 1u;
        } else {
            while (*vg == my) { }
        }
    }
    __syncthreads();
}

// ---------------------------------------------------------------------------
// prep: transpose x[b] (C-major) -> xt (point-major) + squared norms
// ---------------------------------------------------------------------------
__global__ void prep_kernel(const float* __restrict__ x, const float* __restrict__ y,
                            float* __restrict__ xt, float* __restrict__ yt,
                            float* __restrict__ sqx, float* __restrict__ sqy) {
    int p = blockIdx.x * blockDim.x + threadIdx.x;
    float sx = 0.f, sy = 0.f;
    #pragma unroll 8
    for (int c = 0; c < 64; c++) {
        float vx = x[c * NP + p];
        float vy = y[c * NP + p];
        xt[p * 64 + c] = vx;
        yt[p * 64 + c] = vy;
        sx = fmaf(vx, vx, sx);
        sy = fmaf(vy, vy, sy);
    }
    sqx[p] = sx; sqy[p] = sy;
}

// ---------------------------------------------------------------------------
// cost: C[i][j] = 0.5*(|a_i|^2 + |b_j|^2 - 2 a_i.b_j)
// 128x128 tile / block, 256 threads, 8x8 microtile
// ---------------------------------------------------------------------------
__global__ void cost_kernel(const float* __restrict__ A, const float* __restrict__ Bm,
                            const float* __restrict__ sqa, const float* __restrict__ sqb,
                            float* __restrict__ C) {
    __shared__ float As[16 * 128];
    __shared__ float Bs[16 * 128];
    int tid = threadIdx.x;
    int tx = tid & 15, ty = tid >> 4;
    int i0 = blockIdx.y * 128, j0 = blockIdx.x * 128;

    float acc[8][8];
    #pragma unroll
    for (int r = 0; r < 8; r++)
        #pragma unroll
        for (int c = 0; c < 8; c++) acc[r][c] = 0.f;

    for (int c0 = 0; c0 < 64; c0 += 16) {
        #pragma unroll
        for (int n = 0; n < 2; n++) {
            int idx = tid + n * 256;
            int r = idx >> 2, q = idx & 3;
            float4 va = *(const float4*)&A[(size_t)(i0 + r) * 64 + c0 + q * 4];
            As[(q * 4 + 0) * 128 + r] = va.x;
            As[(q * 4 + 1) * 128 + r] = va.y;
            As[(q * 4 + 2) * 128 + r] = va.z;
            As[(q * 4 + 3) * 128 + r] = va.w;
            float4 vb = *(const float4*)&Bm[(size_t)(j0 + r) * 64 + c0 + q * 4];
            Bs[(q * 4 + 0) * 128 + r] = vb.x;
            Bs[(q * 4 + 1) * 128 + r] = vb.y;
            Bs[(q * 4 + 2) * 128 + r] = vb.z;
            Bs[(q * 4 + 3) * 128 + r] = vb.w;
        }
        __syncthreads();
        #pragma unroll
        for (int k = 0; k < 16; k++) {
            float a[8], bb[8];
            *(float4*)&a[0]  = *(const float4*)&As[k * 128 + ty * 8];
            *(float4*)&a[4]  = *(const float4*)&As[k * 128 + ty * 8 + 4];
            *(float4*)&bb[0] = *(const float4*)&Bs[k * 128 + tx * 8];
            *(float4*)&bb[4] = *(const float4*)&Bs[k * 128 + tx * 8 + 4];
            #pragma unroll
            for (int r = 0; r < 8; r++)
                #pragma unroll
                for (int c = 0; c < 8; c++)
                    acc[r][c] = fmaf(a[r], bb[c], acc[r][c]);
        }
        __syncthreads();
    }

    float sj[8];
    #pragma unroll
    for (int c = 0; c < 8; c++) sj[c] = sqb[j0 + tx * 8 + c];

    #pragma unroll
    for (int r = 0; r < 8; r++) {
        int i = i0 + ty * 8 + r;
        float si = sqa[i];
        float o[8];
        #pragma unroll
        for (int c = 0; c < 8; c++)
            o[c] = 0.5f * (si + sj[c] - 2.f * acc[r][c]);
        float* dst = &C[(size_t)i * NP + j0 + tx * 8];
        *(float4*)&dst[0] = *(float4*)&o[0];
        *(float4*)&dst[4] = *(float4*)&o[4];
    }
}

// ---------------------------------------------------------------------------
// exact chunked online-LSE over one row (warp-collective); returns m+log(s)
// on every lane of the warp.
// ---------------------------------------------------------------------------
__device__ __forceinline__ float row_lse(const float4* __restrict__ Cr,
                                         const float4* __restrict__ H4,
                                         float inv_e, int lane) {
    float m = -INFINITY, s = 0.f;
    #pragma unroll
    for (int seg = 0; seg < 8; seg++) {
        float v[16];
        #pragma unroll
        for (int k = 0; k < 4; k++) {
            int q = seg * 128 + k * 32 + lane;
            float4 c = Cr[q];
            float4 h = H4[q];
            v[k * 4 + 0] = fmaf(c.x, -inv_e, h.x);
            v[k * 4 + 1] = fmaf(c.y, -inv_e, h.y);
            v[k * 4 + 2] = fmaf(c.z, -inv_e, h.z);
            v[k * 4 + 3] = fmaf(c.w, -inv_e, h.w);
        }
        float cm = v[0];
        #pragma unroll
        for (int t = 1; t < 16; t++) cm = fmaxf(cm, v[t]);
        float cs = 0.f;
        #pragma unroll
        for (int t = 0; t < 16; t++) cs += __expf(v[t] - cm);
        float nm = fmaxf(m, cm);
        s = s * __expf(m - nm) + cs * __expf(cm - nm);
        m = nm;
    }
    #pragma unroll
    for (int off = 16; off; off >>= 1) {
        float om = __shfl_xor_sync(0xffffffffu, m, off);
        float os = __shfl_xor_sync(0xffffffffu, s, off);
        float nm = fmaxf(m, om);
        s = s * __expf(m - nm) + os * __expf(om - nm);
        m = nm;
    }
    return m + logf(s);
}

__device__ __forceinline__ void init_eps(float* sh_eps, int tid) {
    if (tid < 56) {
        double e = (tid < 55)
            ? exp(5.545177444479562 - 0.21072103131565253 * (double)tid)
            : 0.0025;
        sh_eps[tid] = (float)e;
    }
}

// ---------------------------------------------------------------------------
// symmetric phase (xx or yy): 58 row-softmins with annealing, one launch.
// 256 blocks x 512 threads; warp w of block b owns row b*16+w.
// ---------------------------------------------------------------------------
__global__ void __launch_bounds__(512, 2) sym_phase_kernel(
        const float* __restrict__ C, float* __restrict__ b0, float* __restrict__ b1,
        float* __restrict__ fout) {
    __shared__ __align__(16) float sh[NP];
    __shared__ float sh_eps[56];
    int tid = threadIdx.x, lane = tid & 31, warp = tid >> 5;
    int row = blockIdx.x * 16 + warp;
    init_eps(sh_eps, tid);
    const float4* Cr = (const float4*)(C + (size_t)row * NP);
    float* bufs[2] = { b0, b1 };
    int cur = 0;

    for (int t = 0; t <= 57; t++) {
        __syncthreads();                       // sh_eps ready / sh reuse safe
        int ke = (t == 0) ? 0 : (t == 57 ? 55 : t - 1);
        float e = sh_eps[ke];
        float inv_e = 1.f / e;
        if (t == 0) {
            for (int j = tid; j < NP; j += 512) sh[j] = NEG_LOGN;
        } else {
            const float* pot = bufs[cur];
            for (int j = tid; j < NP; j += 512)
                sh[j] = fmaf(__ldcg(pot + j), inv_e, NEG_LOGN);
        }
        __syncthreads();
        float lse = row_lse(Cr, (const float4*)sh, inv_e, lane);
        if (lane == 0) {
            float val = -e * lse;
            if (t == 57)      fout[row] = val;
            else if (t == 0)  __stcg(&bufs[1][row], val);
            else              __stcg(&bufs[cur ^ 1][row],
                                     0.5f * __ldcg(&bufs[cur][row]) + 0.5f * val);
        }
        if (t == 0) cur = 1; else if (t < 57) cur ^= 1;
        if (t < 57) gsync();
    }
}

// ---------------------------------------------------------------------------
// xy phase: per iteration, row softmin (f update, uses old g) + column
// softmin over C^T (g update, uses old f) via per-block partials + merge.
// Column mapping: block = (colblock cb in [0,8) x 512 cols, rowsplit rs in
// [0,32) x 128 rows). 2 grid barriers / iteration.
// ---------------------------------------------------------------------------
__global__ void __launch_bounds__(512, 2) xy_phase_kernel(
        const float* __restrict__ C,
        float* __restrict__ f0, float* __restrict__ f1,
        float* __restrict__ g0, float* __restrict__ g1,
        float* __restrict__ pm, float* __restrict__ ps,
        float* __restrict__ foutF, float* __restrict__ foutG) {
    __shared__ __align__(16) float shg[NP];
    __shared__ __align__(16) float tile[8 * 512];
    __shared__ float shh[128];
    __shared__ float sh_eps[56];
    int tid = threadIdx.x, lane = tid & 31, warp = tid >> 5;
    int row = blockIdx.x * 16 + warp;
    int cb = blockIdx.x & 7;        // columns [cb*512, cb*512+512)
    int rs = blockIdx.x >> 3;       // rows    [rs*128, rs*128+128)
    init_eps(sh_eps, tid);
    const float4* Cr = (const float4*)(C + (size_t)row * NP);
    float* fb[2] = { f0, f1 };
    float* gb[2] = { g0, g1 };
    int cur = 0;

    for (int t = 0; t <= 57; t++) {
        __syncthreads();
        int ke = (t == 0) ? 0 : (t == 57 ? 55 : t - 1);
        float e = sh_eps[ke];
        float inv_e = 1.f / e;

        // ---- row pass: ft = softmin(e, C, b_log + g/e); write f_next ----
        if (t == 0) {
            for (int j = tid; j < NP; j += 512) shg[j] = NEG_LOGN;
        } else {
            const float* gp = gb[cur];
            for (int j = tid; j < NP; j += 512)
                shg[j] = fmaf(__ldcg(gp + j), inv_e, NEG_LOGN);
        }
        __syncthreads();
        float lse = row_lse(Cr, (const float4*)shg, inv_e, lane);
        if (lane == 0) {
            float val = -e * lse;
            if (t == 57)      foutF[row] = val;
            else if (t == 0)  __stcg(&fb[1][row], val);
            else              __stcg(&fb[cur ^ 1][row],
                                     0.5f * __ldcg(&fb[cur][row]) + 0.5f * val);
        }

        // ---- col partial pass: uses OLD f (fb[cur], untouched above) ----
        __syncthreads();
        if (tid < 128) {
            shh[tid] = (t == 0) ? NEG_LOGN
                : fmaf(__ldcg(&fb[cur][rs * 128 + tid]), inv_e, NEG_LOGN);
        }
        float m = -INFINITY, s = 0.f;
        for (int ch = 0; ch < 16; ch++) {          // 16 chunks of 8 rows
            __syncthreads();
            #pragma unroll
            for (int it = 0; it < 2; it++) {
                int idx = tid + it * 512;          // 0..1023 float4 slots
                int r = idx >> 7, q = idx & 127;
                float4 v = *(const float4*)
                    &C[(size_t)(rs * 128 + ch * 8 + r) * NP + cb * 512 + q * 4];
                *(float4*)&tile[r * 512 + q * 4] = v;
            }
            __syncthreads();
            float v[8];
            #pragma unroll
            for (int r = 0; r < 8; r++)
                v[r] = fmaf(tile[r * 512 + tid], -inv_e, shh[ch * 8 + r]);
            float cm = v[0];
            #pragma unroll
            for (int r = 1; r < 8; r++) cm = fmaxf(cm, v[r]);
            float cs = 0.f;
            #pragma unroll
            for (int r = 0; r < 8; r++) cs += __expf(v[r] - cm);
            float nm = fmaxf(m, cm);
            s = s * __expf(m - nm) + cs * __expf(cm - nm);
            m = nm;
        }
        __stcg(&pm[rs * NP + cb * 512 + tid], m);
        __stcg(&ps[rs * NP + cb * 512 + tid], s);
        gsync();

        // ---- merge col partials -> g update (blocks 0..7 only) ----
        if (blockIdx.x < 8) {
            int j = blockIdx.x * 512 + tid;
            float mm = -INFINITY, ss = 0.f;
            #pragma unroll 8
            for (int r = 0; r < 32; r++) {
                float om = __ldcg(&pm[r * NP + j]);
                float os = __ldcg(&ps[r * NP + j]);
                float nm = fmaxf(mm, om);
                ss = ss * __expf(mm - nm) + os * __expf(om - nm);
                mm = nm;
            }
            float val = -e * (mm + logf(ss));
            if (t == 57)      foutG[j] = val;
            else if (t == 0)  __stcg(&gb[1][j], val);
            else              __stcg(&gb[cur ^ 1][j],
                                     0.5f * __ldcg(&gb[cur][j]) + 0.5f * val);
        }
        if (t == 0) cur = 1; else if (t < 57) cur ^= 1;
        if (t < 57) gsync();
    }
}

// ---------------------------------------------------------------------------
// loss: out (+)= [ mean(fba_f - faa_f) + mean(gab_f - gbb_f) ] / B
// ---------------------------------------------------------------------------
__global__ void loss_reduce(const float* __restrict__ fin, float* __restrict__ out, int first) {
    __shared__ float red[256];
    int tid = threadIdx.x;
    float a = 0.f;
    for (int j = tid; j < NP; j += 256)
        a += (fin[2 * NP + j] - fin[0 * NP + j]) + (fin[3 * NP + j] - fin[1 * NP + j]);
    red[tid] = a;
    __syncthreads();
    for (int sft = 128; sft; sft >>= 1) {
        if (tid < sft) red[tid] += red[tid + sft];
        __syncthreads();
    }
    if (tid == 0) {
        float v = red[0] * (1.0f / NP) * 0.25f;
        if (first) *out = v; else *out += v;
    }
}

// ---------------------------------------------------------------------------
extern "C" void kernel_launch(void* const* d_in, const int* in_sizes, int n_in,
                              void* d_out, int out_size) {
    (void)in_sizes; (void)n_in; (void)out_size;
    const float* x = (const float*)d_in[0];
    const float* y = (const float*)d_in[1];
    float* out = (float*)d_out;

    Scratch* sp = nullptr;
    cudaGetSymbolAddress((void**)&sp, S);
    float* C   = sp->C;
    float* xt  = sp->xt;  float* yt  = sp->yt;
    float* sqx = sp->sqx; float* sqy = sp->sqy;
    float* f0 = sp->f[0]; float* f1 = sp->f[1];
    float* g0 = sp->g[0]; float* g1 = sp->g[1];
    float* fin = (float*)sp->fin;
    float* pm = sp->pm;   float* ps = sp->ps;

    for (int b = 0; b < 4; b++) {
        const float* xb = x + (size_t)b * 64 * NP;
        const float* yb = y + (size_t)b * 64 * NP;
        prep_kernel<<<16, 256>>>(xb, yb, xt, yt, sqx, sqy);

        cost_kernel<<<dim3(32, 32), 256>>>(xt, xt, sqx, sqx, C);
        sym_phase_kernel<<<NBLK, 512>>>(C, f0, f1, fin + 0 * NP);

        cost_kernel<<<dim3(32, 32), 256>>>(yt, yt, sqy, sqy, C);
        sym_phase_kernel<<<NBLK, 512>>>(C, f0, f1, fin + 1 * NP);

        cost_kernel<<<dim3(32, 32), 256>>>(xt, yt, sqx, sqy, C);
        xy_phase_kernel<<<NBLK, 512>>>(C, f0, f1, g0, g1, pm, ps,
                                       fin + 2 * NP, fin + 3 * NP);

        loss_reduce<<<1, 256>>>(fin, out, b == 0 ? 1 : 0);
    }
}

// round 6
// speedup vs baseline: 1.2255x; 1.2255x over previous
#include <cuda_runtime.h>
#include <math.h>

#define NP 4096
#define NBLK 296
#define NEG_LOGN (-8.317766166719343f)   /* -log(4096) */
#define LOG2E 1.4426950408889634f
#define LN2   0.6931471805599453f

struct __align__(16) Scratch {
    float C[(size_t)NP * NP];      // 64 MB cost matrix
    float CT[(size_t)NP * NP];     // 64 MB transposed cost (xy phase only)
    float xt[NP * 64], yt[NP * 64];
    float sqx[NP], sqy[NP];
    float f[2][NP], g[2][NP];      // ping-pong potentials
    float fin[4][NP];              // faa_f, gbb_f, fba_f, gab_f
};
__device__ Scratch S;

// ---------------------------------------------------------------------------
// software grid barrier (all NBLK blocks co-resident: 2 blocks / SM exactly)
// ---------------------------------------------------------------------------
__device__ unsigned g_cnt;
__device__ unsigned g_gen;

__device__ __forceinline__ void gsync() {
    __threadfence();
    __syncthreads();
    if (threadIdx.x == 0) {
        volatile unsigned* vg = &g_gen;
        unsigned my = *vg;
        if (atomicAdd(&g_cnt, 1u) == NBLK - 1u) {
            g_cnt = 0u;
            __threadfence();
            *vg = my + 1u;
        } else {
            while (*vg == my) { }
        }
    }
    __syncthreads();
}

// ---------------------------------------------------------------------------
// prep: transpose x[b] (C-major) -> xt (point-major) + squared norms
// ---------------------------------------------------------------------------
__global__ void prep_kernel(const float* __restrict__ x, const float* __restrict__ y,
                            float* __restrict__ xt, float* __restrict__ yt,
                            float* __restrict__ sqx, float* __restrict__ sqy) {
    int p = blockIdx.x * blockDim.x + threadIdx.x;
    float sx = 0.f, sy = 0.f;
    #pragma unroll 8
    for (int c = 0; c < 64; c++) {
        float vx = x[c * NP + p];
        float vy = y[c * NP + p];
        xt[p * 64 + c] = vx;
        yt[p * 64 + c] = vy;
        sx = fmaf(vx, vx, sx);
        sy = fmaf(vy, vy, sy);
    }
    sqx[p] = sx; sqy[p] = sy;
}

// ---------------------------------------------------------------------------
// cost: C[i][j] = 0.5*(|a_i|^2 + |b_j|^2 - 2 a_i.b_j)
// ---------------------------------------------------------------------------
__global__ void cost_kernel(const float* __restrict__ A, const float* __restrict__ Bm,
                            const float* __restrict__ sqa, const float* __restrict__ sqb,
                            float* __restrict__ C) {
    __shared__ float As[16 * 128];
    __shared__ float Bs[16 * 128];
    int tid = threadIdx.x;
    int tx = tid & 15, ty = tid >> 4;
    int i0 = blockIdx.y * 128, j0 = blockIdx.x * 128;

    float acc[8][8];
    #pragma unroll
    for (int r = 0; r < 8; r++)
        #pragma unroll
        for (int c = 0; c < 8; c++) acc[r][c] = 0.f;

    for (int c0 = 0; c0 < 64; c0 += 16) {
        #pragma unroll
        for (int n = 0; n < 2; n++) {
            int idx = tid + n * 256;
            int r = idx >> 2, q = idx & 3;
            float4 va = *(const float4*)&A[(size_t)(i0 + r) * 64 + c0 + q * 4];
            As[(q * 4 + 0) * 128 + r] = va.x;
            As[(q * 4 + 1) * 128 + r] = va.y;
            As[(q * 4 + 2) * 128 + r] = va.z;
            As[(q * 4 + 3) * 128 + r] = va.w;
            float4 vb = *(const float4*)&Bm[(size_t)(j0 + r) * 64 + c0 + q * 4];
            Bs[(q * 4 + 0) * 128 + r] = vb.x;
            Bs[(q * 4 + 1) * 128 + r] = vb.y;
            Bs[(q * 4 + 2) * 128 + r] = vb.z;
            Bs[(q * 4 + 3) * 128 + r] = vb.w;
        }
        __syncthreads();
        #pragma unroll
        for (int k = 0; k < 16; k++) {
            float a[8], bb[8];
            *(float4*)&a[0]  = *(const float4*)&As[k * 128 + ty * 8];
            *(float4*)&a[4]  = *(const float4*)&As[k * 128 + ty * 8 + 4];
            *(float4*)&bb[0] = *(const float4*)&Bs[k * 128 + tx * 8];
            *(float4*)&bb[4] = *(const float4*)&Bs[k * 128 + tx * 8 + 4];
            #pragma unroll
            for (int r = 0; r < 8; r++)
                #pragma unroll
                for (int c = 0; c < 8; c++)
                    acc[r][c] = fmaf(a[r], bb[c], acc[r][c]);
        }
        __syncthreads();
    }

    float sj[8];
    #pragma unroll
    for (int c = 0; c < 8; c++) sj[c] = sqb[j0 + tx * 8 + c];

    #pragma unroll
    for (int r = 0; r < 8; r++) {
        int i = i0 + ty * 8 + r;
        float si = sqa[i];
        float o[8];
        #pragma unroll
        for (int c = 0; c < 8; c++)
            o[c] = 0.5f * (si + sj[c] - 2.f * acc[r][c]);
        float* dst = &C[(size_t)i * NP + j0 + tx * 8];
        *(float4*)&dst[0] = *(float4*)&o[0];
        *(float4*)&dst[4] = *(float4*)&o[4];
    }
}

// ---------------------------------------------------------------------------
// transpose C -> CT (32x32 smem tiles)
// ---------------------------------------------------------------------------
__global__ void transpose_kernel(const float* __restrict__ A, float* __restrict__ B) {
    __shared__ float t[32][33];
    int x = blockIdx.x * 32 + threadIdx.x;
    int y = blockIdx.y * 32 + threadIdx.y;
    #pragma unroll
    for (int j = 0; j < 32; j += 8)
        t[threadIdx.y + j][threadIdx.x] = A[(size_t)(y + j) * NP + x];
    __syncthreads();
    x = blockIdx.y * 32 + threadIdx.x;
    y = blockIdx.x * 32 + threadIdx.y;
    #pragma unroll
    for (int j = 0; j < 32; j += 8)
        B[(size_t)(y + j) * NP + x] = t[threadIdx.x][threadIdx.y + j];
}

// ---------------------------------------------------------------------------
// exact chunked online-LSE over one row in base-2, warp-collective.
// H4 is pre-scaled by LOG2E; k = -LOG2E/eps. Returns m + log2(s).
// Double-buffered 64B C prefetch per 16-element chunk.
// ---------------------------------------------------------------------------
template<bool STREAM>
__device__ __forceinline__ float4 ldC4(const float4* p) {
    return STREAM ? __ldcs(p) : *p;
}

template<bool STREAM>
__device__ __forceinline__ float row_lse2(const float4* __restrict__ Cr,
                                          const float4* __restrict__ H4,
                                          float k, int lane) {
    float4 c0 = ldC4<STREAM>(Cr + lane);
    float4 c1 = ldC4<STREAM>(Cr + 32 + lane);
    float4 c2 = ldC4<STREAM>(Cr + 64 + lane);
    float4 c3 = ldC4<STREAM>(Cr + 96 + lane);
    float m = -INFINITY, s = 0.f;
    #pragma unroll
    for (int seg = 0; seg < 8; seg++) {
        float4 n0, n1, n2, n3;
        if (seg < 7) {
            int b = (seg + 1) * 128 + lane;
            n0 = ldC4<STREAM>(Cr + b);
            n1 = ldC4<STREAM>(Cr + b + 32);
            n2 = ldC4<STREAM>(Cr + b + 64);
            n3 = ldC4<STREAM>(Cr + b + 96);
        }
        int hb = seg * 128 + lane;
        float4 h0 = H4[hb], h1 = H4[hb + 32], h2 = H4[hb + 64], h3 = H4[hb + 96];
        float v[16];
        v[0]  = fmaf(c0.x, k, h0.x); v[1]  = fmaf(c0.y, k, h0.y);
        v[2]  = fmaf(c0.z, k, h0.z); v[3]  = fmaf(c0.w, k, h0.w);
        v[4]  = fmaf(c1.x, k, h1.x); v[5]  = fmaf(c1.y, k, h1.y);
        v[6]  = fmaf(c1.z, k, h1.z); v[7]  = fmaf(c1.w, k, h1.w);
        v[8]  = fmaf(c2.x, k, h2.x); v[9]  = fmaf(c2.y, k, h2.y);
        v[10] = fmaf(c2.z, k, h2.z); v[11] = fmaf(c2.w, k, h2.w);
        v[12] = fmaf(c3.x, k, h3.x); v[13] = fmaf(c3.y, k, h3.y);
        v[14] = fmaf(c3.z, k, h3.z); v[15] = fmaf(c3.w, k, h3.w);
        float cm = v[0];
        #pragma unroll
        for (int t = 1; t < 16; t++) cm = fmaxf(cm, v[t]);
        float cs = 0.f;
        #pragma unroll
        for (int t = 0; t < 16; t++) cs += exp2f(v[t] - cm);
        float nm = fmaxf(m, cm);
        s = s * exp2f(m - nm) + cs * exp2f(cm - nm);
        m = nm;
        c0 = n0; c1 = n1; c2 = n2; c3 = n3;
    }
    #pragma unroll
    for (int off = 16; off; off >>= 1) {
        float om = __shfl_xor_sync(0xffffffffu, m, off);
        float os = __shfl_xor_sync(0xffffffffu, s, off);
        float nm = fmaxf(m, om);
        s = s * exp2f(m - nm) + os * exp2f(om - nm);
        m = nm;
    }
    return m + log2f(s);
}

__device__ __forceinline__ void init_eps(float* sh_eps, int tid) {
    if (tid < 56) {
        double e = (tid < 55)
            ? exp(5.545177444479562 - 0.21072103131565253 * (double)tid)
            : 0.0025;
        sh_eps[tid] = (float)e;
    }
}

// ---------------------------------------------------------------------------
// symmetric phase (xx or yy): 58 row-softmins with annealing, one launch.
// NBLK=296 blocks x 512 threads; warp w of block bi owns row w*296+bi (<NP).
// ---------------------------------------------------------------------------
__global__ void __launch_bounds__(512, 2) sym_phase_kernel(
        const float* __restrict__ C, float* __restrict__ b0, float* __restrict__ b1,
        float* __restrict__ fout) {
    __shared__ __align__(16) float sh[NP];
    __shared__ float sh_eps[56];
    int tid = threadIdx.x, lane = tid & 31, warp = tid >> 5;
    int row = warp * NBLK + (int)blockIdx.x;
    bool active = row < NP;
    int prow = active ? row : 0;
    init_eps(sh_eps, tid);
    const float4* Cr = (const float4*)(C + (size_t)prow * NP);
    float* bufs[2] = { b0, b1 };
    int cur = 0;

    for (int t = 0; t <= 57; t++) {
        __syncthreads();
        int ke = (t == 0) ? 0 : (t == 57 ? 55 : t - 1);
        float e = sh_eps[ke];
        float inv_e = 1.f / e;
        float k = -inv_e * LOG2E;
        if (t == 0) {
            for (int j = tid; j < NP; j += 512) sh[j] = NEG_LOGN * LOG2E;
        } else {
            const float* pot = bufs[cur];
            for (int j = tid; j < NP; j += 512)
                sh[j] = fmaf(__ldcg(pot + j), inv_e, NEG_LOGN) * LOG2E;
        }
        __syncthreads();
        float lse = row_lse2<false>(Cr, (const float4*)sh, k, lane);
        if (lane == 0 && active) {
            float val = -e * LN2 * lse;
            if (t == 57)      fout[row] = val;
            else if (t == 0)  __stcg(&bufs[1][row], val);
            else              __stcg(&bufs[cur ^ 1][row],
                                     0.5f * __ldcg(&bufs[cur][row]) + 0.5f * val);
        }
        if (t == 0) cur = 1; else if (t < 57) cur ^= 1;
        if (t < 57) gsync();
    }
}

// ---------------------------------------------------------------------------
// xy phase: each warp owns row r of BOTH C (f-update, reads old g) and
// CT (g-update, reads old f). One grid barrier per iteration.
// C kept L2-resident; CT streamed with __ldcs so it doesn't evict C.
// ---------------------------------------------------------------------------
__global__ void __launch_bounds__(512, 2) xy_phase_kernel(
        const float* __restrict__ C, const float* __restrict__ CT,
        float* __restrict__ f0, float* __restrict__ f1,
        float* __restrict__ g0, float* __restrict__ g1,
        float* __restrict__ foutF, float* __restrict__ foutG) {
    __shared__ __align__(16) float shg[NP];
    __shared__ __align__(16) float shf[NP];
    __shared__ float sh_eps[56];
    int tid = threadIdx.x, lane = tid & 31, warp = tid >> 5;
    int row = warp * NBLK + (int)blockIdx.x;
    bool active = row < NP;
    int prow = active ? row : 0;
    init_eps(sh_eps, tid);
    const float4* Cr  = (const float4*)(C  + (size_t)prow * NP);
    const float4* CTr = (const float4*)(CT + (size_t)prow * NP);
    float* fb[2] = { f0, f1 };
    float* gb[2] = { g0, g1 };
    int cur = 0;

    for (int t = 0; t <= 57; t++) {
        __syncthreads();
        int ke = (t == 0) ? 0 : (t == 57 ? 55 : t - 1);
        float e = sh_eps[ke];
        float inv_e = 1.f / e;
        float k = -inv_e * LOG2E;

        if (t == 0) {
            for (int j = tid; j < NP; j += 512) {
                shg[j] = NEG_LOGN * LOG2E;
                shf[j] = NEG_LOGN * LOG2E;
            }
        } else {
            const float* gp = gb[cur];
            const float* fp = fb[cur];
            for (int j = tid; j < NP; j += 512) {
                shg[j] = fmaf(__ldcg(gp + j), inv_e, NEG_LOGN) * LOG2E;
                shf[j] = fmaf(__ldcg(fp + j), inv_e, NEG_LOGN) * LOG2E;
            }
        }
        __syncthreads();

        float lseF = row_lse2<false>(Cr,  (const float4*)shg, k, lane);
        float lseG = row_lse2<true >(CTr, (const float4*)shf, k, lane);

        if (lane == 0 && active) {
            float valF = -e * LN2 * lseF;
            float valG = -e * LN2 * lseG;
            if (t == 57) {
                foutF[row] = valF;
                foutG[row] = valG;
            } else if (t == 0) {
                __stcg(&fb[1][row], valF);
                __stcg(&gb[1][row], valG);
            } else {
                __stcg(&fb[cur ^ 1][row],
                       0.5f * __ldcg(&fb[cur][row]) + 0.5f * valF);
                __stcg(&gb[cur ^ 1][row],
                       0.5f * __ldcg(&gb[cur][row]) + 0.5f * valG);
            }
        }
        if (t == 0) cur = 1; else if (t < 57) cur ^= 1;
        if (t < 57) gsync();
    }
}

// ---------------------------------------------------------------------------
// loss: out (+)= [ mean(fba_f - faa_f) + mean(gab_f - gbb_f) ] / B
// ---------------------------------------------------------------------------
__global__ void loss_reduce(const float* __restrict__ fin, float* __restrict__ out, int first) {
    __shared__ float red[256];
    int tid = threadIdx.x;
    float a = 0.f;
    for (int j = tid; j < NP; j += 256)
        a += (fin[2 * NP + j] - fin[0 * NP + j]) + (fin[3 * NP + j] - fin[1 * NP + j]);
    red[tid] = a;
    __syncthreads();
    for (int sft = 128; sft; sft >>= 1) {
        if (tid < sft) red[tid] += red[tid + sft];
        __syncthreads();
    }
    if (tid == 0) {
        float v = red[0] * (1.0f / NP) * 0.25f;
        if (first) *out = v; else *out += v;
    }
}

// ---------------------------------------------------------------------------
extern "C" void kernel_launch(void* const* d_in, const int* in_sizes, int n_in,
                              void* d_out, int out_size) {
    (void)in_sizes; (void)n_in; (void)out_size;
    const float* x = (const float*)d_in[0];
    const float* y = (const float*)d_in[1];
    float* out = (float*)d_out;

    Scratch* sp = nullptr;
    cudaGetSymbolAddress((void**)&sp, S);
    float* C   = sp->C;   float* CT = sp->CT;
    float* xt  = sp->xt;  float* yt  = sp->yt;
    float* sqx = sp->sqx; float* sqy = sp->sqy;
    float* f0 = sp->f[0]; float* f1 = sp->f[1];
    float* g0 = sp->g[0]; float* g1 = sp->g[1];
    float* fin = (float*)sp->fin;

    for (int b = 0; b < 4; b++) {
        const float* xb = x + (size_t)b * 64 * NP;
        const float* yb = y + (size_t)b * 64 * NP;
        prep_kernel<<<16, 256>>>(xb, yb, xt, yt, sqx, sqy);

        cost_kernel<<<dim3(32, 32), 256>>>(xt, xt, sqx, sqx, C);
        sym_phase_kernel<<<NBLK, 512>>>(C, f0, f1, fin + 0 * NP);

        cost_kernel<<<dim3(32, 32), 256>>>(yt, yt, sqy, sqy, C);
        sym_phase_kernel<<<NBLK, 512>>>(C, f0, f1, fin + 1 * NP);

        cost_kernel<<<dim3(32, 32), 256>>>(xt, yt, sqx, sqy, C);
        transpose_kernel<<<dim3(128, 128), dim3(32, 8)>>>(C, CT);
        xy_phase_kernel<<<NBLK, 512>>>(C, CT, f0, f1, g0, g1,
                                       fin + 2 * NP, fin + 3 * NP);

        loss_reduce<<<1, 256>>>(fin, out, b == 0 ? 1 : 0);
    }
}

// round 7
// speedup vs baseline: 1.2951x; 1.0568x over previous
#include <cuda_runtime.h>
#include <math.h>

#define NP 4096
#define NBLK 296
#define NEG_LOGN (-8.317766166719343f)   /* -log(4096) */
#define LOG2E 1.4426950408889634f
#define LN2   0.6931471805599453f

struct __align__(16) Scratch {
    float Cxx[(size_t)NP * NP];    // 64 MB
    float Cyy[(size_t)NP * NP];    // 64 MB
    float C  [(size_t)NP * NP];    // 64 MB (xy)
    float CT [(size_t)NP * NP];    // 64 MB (xy transposed)
    float xt[NP * 64], yt[NP * 64];
    float sqx[NP], sqy[NP];
    float f[2][NP], g[2][NP];      // ping-pong potentials
    float fin[4][NP];              // faa_f, gbb_f, fba_f, gab_f
};
__device__ Scratch S;

// ---------------------------------------------------------------------------
// software grid barrier (all NBLK blocks co-resident: 2 blocks / SM exactly)
// ---------------------------------------------------------------------------
__device__ unsigned g_cnt;
__device__ unsigned g_gen;

__device__ __forceinline__ void gsync() {
    __threadfence();
    __syncthreads();
    if (threadIdx.x == 0) {
        volatile unsigned* vg = &g_gen;
        unsigned my = *vg;
        if (atomicAdd(&g_cnt, 1u) == NBLK - 1u) {
            g_cnt = 0u;
            __threadfence();
            *vg = my + 1u;
        } else {
            while (*vg == my) { __nanosleep(32); }
        }
    }
    __syncthreads();
}

// ---------------------------------------------------------------------------
// prep: transpose x[b] (C-major) -> xt (point-major) + squared norms
// ---------------------------------------------------------------------------
__global__ void prep_kernel(const float* __restrict__ x, const float* __restrict__ y,
                            float* __restrict__ xt, float* __restrict__ yt,
                            float* __restrict__ sqx, float* __restrict__ sqy) {
    int p = blockIdx.x * blockDim.x + threadIdx.x;
    float sx = 0.f, sy = 0.f;
    #pragma unroll 8
    for (int c = 0; c < 64; c++) {
        float vx = x[c * NP + p];
        float vy = y[c * NP + p];
        xt[p * 64 + c] = vx;
        yt[p * 64 + c] = vy;
        sx = fmaf(vx, vx, sx);
        sy = fmaf(vy, vy, sy);
    }
    sqx[p] = sx; sqy[p] = sy;
}

// ---------------------------------------------------------------------------
// cost: C[i][j] = 0.5*(|a_i|^2 + |b_j|^2 - 2 a_i.b_j)
// ---------------------------------------------------------------------------
__global__ void cost_kernel(const float* __restrict__ A, const float* __restrict__ Bm,
                            const float* __restrict__ sqa, const float* __restrict__ sqb,
                            float* __restrict__ C) {
    __shared__ float As[16 * 128];
    __shared__ float Bs[16 * 128];
    int tid = threadIdx.x;
    int tx = tid & 15, ty = tid >> 4;
    int i0 = blockIdx.y * 128, j0 = blockIdx.x * 128;

    float acc[8][8];
    #pragma unroll
    for (int r = 0; r < 8; r++)
        #pragma unroll
        for (int c = 0; c < 8; c++) acc[r][c] = 0.f;

    for (int c0 = 0; c0 < 64; c0 += 16) {
        #pragma unroll
        for (int n = 0; n < 2; n++) {
            int idx = tid + n * 256;
            int r = idx >> 2, q = idx & 3;
            float4 va = *(const float4*)&A[(size_t)(i0 + r) * 64 + c0 + q * 4];
            As[(q * 4 + 0) * 128 + r] = va.x;
            As[(q * 4 + 1) * 128 + r] = va.y;
            As[(q * 4 + 2) * 128 + r] = va.z;
            As[(q * 4 + 3) * 128 + r] = va.w;
            float4 vb = *(const float4*)&Bm[(size_t)(j0 + r) * 64 + c0 + q * 4];
            Bs[(q * 4 + 0) * 128 + r] = vb.x;
            Bs[(q * 4 + 1) * 128 + r] = vb.y;
            Bs[(q * 4 + 2) * 128 + r] = vb.z;
            Bs[(q * 4 + 3) * 128 + r] = vb.w;
        }
        __syncthreads();
        #pragma unroll
        for (int k = 0; k < 16; k++) {
            float a[8], bb[8];
            *(float4*)&a[0]  = *(const float4*)&As[k * 128 + ty * 8];
            *(float4*)&a[4]  = *(const float4*)&As[k * 128 + ty * 8 + 4];
            *(float4*)&bb[0] = *(const float4*)&Bs[k * 128 + tx * 8];
            *(float4*)&bb[4] = *(const float4*)&Bs[k * 128 + tx * 8 + 4];
            #pragma unroll
            for (int r = 0; r < 8; r++)
                #pragma unroll
                for (int c = 0; c < 8; c++)
                    acc[r][c] = fmaf(a[r], bb[c], acc[r][c]);
        }
        __syncthreads();
    }

    float sj[8];
    #pragma unroll
    for (int c = 0; c < 8; c++) sj[c] = sqb[j0 + tx * 8 + c];

    #pragma unroll
    for (int r = 0; r < 8; r++) {
        int i = i0 + ty * 8 + r;
        float si = sqa[i];
        float o[8];
        #pragma unroll
        for (int c = 0; c < 8; c++)
            o[c] = 0.5f * (si + sj[c] - 2.f * acc[r][c]);
        float* dst = &C[(size_t)i * NP + j0 + tx * 8];
        *(float4*)&dst[0] = *(float4*)&o[0];
        *(float4*)&dst[4] = *(float4*)&o[4];
    }
}

// ---------------------------------------------------------------------------
// transpose C -> CT (32x32 smem tiles)
// ---------------------------------------------------------------------------
__global__ void transpose_kernel(const float* __restrict__ A, float* __restrict__ B) {
    __shared__ float t[32][33];
    int x = blockIdx.x * 32 + threadIdx.x;
    int y = blockIdx.y * 32 + threadIdx.y;
    #pragma unroll
    for (int j = 0; j < 32; j += 8)
        t[threadIdx.y + j][threadIdx.x] = A[(size_t)(y + j) * NP + x];
    __syncthreads();
    x = blockIdx.y * 32 + threadIdx.x;
    y = blockIdx.x * 32 + threadIdx.y;
    #pragma unroll
    for (int j = 0; j < 32; j += 8)
        B[(size_t)(y + j) * NP + x] = t[threadIdx.x][threadIdx.y + j];
}

// ---------------------------------------------------------------------------
// exact chunked online-LSE (base-2). H pre-scaled by LOG2E; k = -LOG2E/eps.
// Single-stream version with double-buffered prefetch (sym phase).
// ---------------------------------------------------------------------------
__device__ __forceinline__ float row_lse2(const float4* __restrict__ Cr,
                                          const float4* __restrict__ H4,
                                          float k, int lane) {
    float4 c0 = Cr[lane];
    float4 c1 = Cr[32 + lane];
    float4 c2 = Cr[64 + lane];
    float4 c3 = Cr[96 + lane];
    float m = -INFINITY, s = 0.f;
    #pragma unroll
    for (int seg = 0; seg < 8; seg++) {
        float4 n0, n1, n2, n3;
        if (seg < 7) {
            int b = (seg + 1) * 128 + lane;
            n0 = Cr[b]; n1 = Cr[b + 32]; n2 = Cr[b + 64]; n3 = Cr[b + 96];
        }
        int hb = seg * 128 + lane;
        float4 h0 = H4[hb], h1 = H4[hb + 32], h2 = H4[hb + 64], h3 = H4[hb + 96];
        float v[16];
        v[0]  = fmaf(c0.x, k, h0.x); v[1]  = fmaf(c0.y, k, h0.y);
        v[2]  = fmaf(c0.z, k, h0.z); v[3]  = fmaf(c0.w, k, h0.w);
        v[4]  = fmaf(c1.x, k, h1.x); v[5]  = fmaf(c1.y, k, h1.y);
        v[6]  = fmaf(c1.z, k, h1.z); v[7]  = fmaf(c1.w, k, h1.w);
        v[8]  = fmaf(c2.x, k, h2.x); v[9]  = fmaf(c2.y, k, h2.y);
        v[10] = fmaf(c2.z, k, h2.z); v[11] = fmaf(c2.w, k, h2.w);
        v[12] = fmaf(c3.x, k, h3.x); v[13] = fmaf(c3.y, k, h3.y);
        v[14] = fmaf(c3.z, k, h3.z); v[15] = fmaf(c3.w, k, h3.w);
        float cm = v[0];
        #pragma unroll
        for (int t = 1; t < 16; t++) cm = fmaxf(cm, v[t]);
        float cs = 0.f;
        #pragma unroll
        for (int t = 0; t < 16; t++) cs += exp2f(v[t] - cm);
        float nm = fmaxf(m, cm);
        s = s * exp2f(m - nm) + cs * exp2f(cm - nm);
        m = nm;
        c0 = n0; c1 = n1; c2 = n2; c3 = n3;
    }
    #pragma unroll
    for (int off = 16; off; off >>= 1) {
        float om = __shfl_xor_sync(0xffffffffu, m, off);
        float os = __shfl_xor_sync(0xffffffffu, s, off);
        float nm = fmaxf(m, om);
        s = s * exp2f(m - nm) + os * exp2f(om - nm);
        m = nm;
    }
    return m + log2f(s);
}

// ---------------------------------------------------------------------------
// dual-stream LSE: stream A (default policy) and stream B (__ldcs streaming),
// chunk-interleaved so both matrices' loads are in flight together.
// Returns (lseA, lseB).
// ---------------------------------------------------------------------------
__device__ __forceinline__ void chunk16(const float4* c, const float4* h,
                                        float k, float& m, float& s) {
    float v[16];
    #pragma unroll
    for (int q = 0; q < 4; q++) {
        v[q*4+0] = fmaf(c[q].x, k, h[q].x);
        v[q*4+1] = fmaf(c[q].y, k, h[q].y);
        v[q*4+2] = fmaf(c[q].z, k, h[q].z);
        v[q*4+3] = fmaf(c[q].w, k, h[q].w);
    }
    float cm = v[0];
    #pragma unroll
    for (int t = 1; t < 16; t++) cm = fmaxf(cm, v[t]);
    float cs = 0.f;
    #pragma unroll
    for (int t = 0; t < 16; t++) cs += exp2f(v[t] - cm);
    float nm = fmaxf(m, cm);
    s = s * exp2f(m - nm) + cs * exp2f(cm - nm);
    m = nm;
}

__device__ __forceinline__ float2 row_lse2_dual(
        const float4* __restrict__ CrA, const float4* __restrict__ CrB,
        const float4* __restrict__ HA,  const float4* __restrict__ HB,
        float k, int lane) {
    float mA = -INFINITY, sA = 0.f;
    float mB = -INFINITY, sB = 0.f;
    #pragma unroll
    for (int seg = 0; seg < 8; seg++) {
        int b = seg * 128 + lane;
        float4 a[4], bb[4];
        a[0]  = CrA[b];      a[1]  = CrA[b + 32];
        a[2]  = CrA[b + 64]; a[3]  = CrA[b + 96];
        bb[0] = __ldcs(CrB + b);      bb[1] = __ldcs(CrB + b + 32);
        bb[2] = __ldcs(CrB + b + 64); bb[3] = __ldcs(CrB + b + 96);
        float4 ha[4], hb4[4];
        ha[0]  = HA[b];      ha[1]  = HA[b + 32];
        ha[2]  = HA[b + 64]; ha[3]  = HA[b + 96];
        hb4[0] = HB[b];      hb4[1] = HB[b + 32];
        hb4[2] = HB[b + 64]; hb4[3] = HB[b + 96];
        chunk16(a,  ha,  k, mA, sA);
        chunk16(bb, hb4, k, mB, sB);
    }
    #pragma unroll
    for (int off = 16; off; off >>= 1) {
        float om = __shfl_xor_sync(0xffffffffu, mA, off);
        float os = __shfl_xor_sync(0xffffffffu, sA, off);
        float nm = fmaxf(mA, om);
        sA = sA * exp2f(mA - nm) + os * exp2f(om - nm);
        mA = nm;
        float om2 = __shfl_xor_sync(0xffffffffu, mB, off);
        float os2 = __shfl_xor_sync(0xffffffffu, sB, off);
        float nm2 = fmaxf(mB, om2);
        sB = sB * exp2f(mB - nm2) + os2 * exp2f(om2 - nm2);
        mB = nm2;
    }
    return make_float2(mA + log2f(sA), mB + log2f(sB));
}

__device__ __forceinline__ void init_eps(float* sh_eps, int tid) {
    if (tid < 56) {
        double e = (tid < 55)
            ? exp(5.545177444479562 - 0.21072103131565253 * (double)tid)
            : 0.0025;
        sh_eps[tid] = (float)e;
    }
}

// h-prefill: sh[j] = (pot[j]/eps + NEG_LOGN) * LOG2E, float4-wide
__device__ __forceinline__ void fill_bias(float* sh, const float* pot,
                                          float inv_e, int tid) {
    const float4* p4 = (const float4*)pot;
    float4* s4 = (float4*)sh;
    #pragma unroll
    for (int q = 0; q < 2; q++) {
        int j = tid + q * 512;
        float4 v = __ldcg(p4 + j);
        float4 o;
        o.x = fmaf(v.x, inv_e, NEG_LOGN) * LOG2E;
        o.y = fmaf(v.y, inv_e, NEG_LOGN) * LOG2E;
        o.z = fmaf(v.z, inv_e, NEG_LOGN) * LOG2E;
        o.w = fmaf(v.w, inv_e, NEG_LOGN) * LOG2E;
        s4[j] = o;
    }
}

// ---------------------------------------------------------------------------
// symmetric phase (xx or yy): 58 row-softmins with annealing, one launch.
// ---------------------------------------------------------------------------
__global__ void __launch_bounds__(512, 2) sym_phase_kernel(
        const float* __restrict__ C, float* __restrict__ b0, float* __restrict__ b1,
        float* __restrict__ fout) {
    __shared__ __align__(16) float sh[NP];
    __shared__ float sh_eps[56];
    int tid = threadIdx.x, lane = tid & 31, warp = tid >> 5;
    int row = warp * NBLK + (int)blockIdx.x;
    bool active = row < NP;
    int prow = active ? row : 0;
    init_eps(sh_eps, tid);
    const float4* Cr = (const float4*)(C + (size_t)prow * NP);
    float* bufs[2] = { b0, b1 };
    int cur = 0;

    for (int t = 0; t <= 57; t++) {
        __syncthreads();
        int ke = (t == 0) ? 0 : (t == 57 ? 55 : t - 1);
        float e = sh_eps[ke];
        float inv_e = 1.f / e;
        float k = -inv_e * LOG2E;
        if (t == 0) {
            for (int j = tid; j < NP; j += 512) sh[j] = NEG_LOGN * LOG2E;
        } else {
            fill_bias(sh, bufs[cur], inv_e, tid);
        }
        __syncthreads();
        float lse = row_lse2(Cr, (const float4*)sh, k, lane);
        if (lane == 0 && active) {
            float val = -e * LN2 * lse;
            if (t == 57)      fout[row] = val;
            else if (t == 0)  __stcg(&bufs[1][row], val);
            else              __stcg(&bufs[cur ^ 1][row],
                                     0.5f * __ldcg(&bufs[cur][row]) + 0.5f * val);
        }
        if (t == 0) cur = 1; else if (t < 57) cur ^= 1;
        if (t < 57) gsync();
    }
}

// ---------------------------------------------------------------------------
// xy phase: dual-stream (C row -> f, CT row -> g), chunk-interleaved.
// ---------------------------------------------------------------------------
__global__ void __launch_bounds__(512, 2) xy_phase_kernel(
        const float* __restrict__ C, const float* __restrict__ CT,
        float* __restrict__ f0, float* __restrict__ f1,
        float* __restrict__ g0, float* __restrict__ g1,
        float* __restrict__ foutF, float* __restrict__ foutG) {
    __shared__ __align__(16) float shg[NP];
    __shared__ __align__(16) float shf[NP];
    __shared__ float sh_eps[56];
    int tid = threadIdx.x, lane = tid & 31, warp = tid >> 5;
    int row = warp * NBLK + (int)blockIdx.x;
    bool active = row < NP;
    int prow = active ? row : 0;
    init_eps(sh_eps, tid);
    const float4* Cr  = (const float4*)(C  + (size_t)prow * NP);
    const float4* CTr = (const float4*)(CT + (size_t)prow * NP);
    float* fb[2] = { f0, f1 };
    float* gb[2] = { g0, g1 };
    int cur = 0;

    for (int t = 0; t <= 57; t++) {
        __syncthreads();
        int ke = (t == 0) ? 0 : (t == 57 ? 55 : t - 1);
        float e = sh_eps[ke];
        float inv_e = 1.f / e;
        float k = -inv_e * LOG2E;

        if (t == 0) {
            for (int j = tid; j < NP; j += 512) {
                shg[j] = NEG_LOGN * LOG2E;
                shf[j] = NEG_LOGN * LOG2E;
            }
        } else {
            fill_bias(shg, gb[cur], inv_e, tid);
            fill_bias(shf, fb[cur], inv_e, tid);
        }
        __syncthreads();

        float2 ls = row_lse2_dual(Cr, CTr, (const float4*)shg,
                                  (const float4*)shf, k, lane);

        if (lane == 0 && active) {
            float valF = -e * LN2 * ls.x;
            float valG = -e * LN2 * ls.y;
            if (t == 57) {
                foutF[row] = valF;
                foutG[row] = valG;
            } else if (t == 0) {
                __stcg(&fb[1][row], valF);
                __stcg(&gb[1][row], valG);
            } else {
                __stcg(&fb[cur ^ 1][row],
                       0.5f * __ldcg(&fb[cur][row]) + 0.5f * valF);
                __stcg(&gb[cur ^ 1][row],
                       0.5f * __ldcg(&gb[cur][row]) + 0.5f * valG);
            }
        }
        if (t == 0) cur = 1; else if (t < 57) cur ^= 1;
        if (t < 57) gsync();
    }
}

// ---------------------------------------------------------------------------
// loss: out (+)= [ mean(fba_f - faa_f) + mean(gab_f - gbb_f) ] / B
// ---------------------------------------------------------------------------
__global__ void loss_reduce(const float* __restrict__ fin, float* __restrict__ out, int first) {
    __shared__ float red[256];
    int tid = threadIdx.x;
    float a = 0.f;
    for (int j = tid; j < NP; j += 256)
        a += (fin[2 * NP + j] - fin[0 * NP + j]) + (fin[3 * NP + j] - fin[1 * NP + j]);
    red[tid] = a;
    __syncthreads();
    for (int sft = 128; sft; sft >>= 1) {
        if (tid < sft) red[tid] += red[tid + sft];
        __syncthreads();
    }
    if (tid == 0) {
        float v = red[0] * (1.0f / NP) * 0.25f;
        if (first) *out = v; else *out += v;
    }
}

// ---------------------------------------------------------------------------
extern "C" void kernel_launch(void* const* d_in, const int* in_sizes, int n_in,
                              void* d_out, int out_size) {
    (void)in_sizes; (void)n_in; (void)out_size;
    const float* x = (const float*)d_in[0];
    const float* y = (const float*)d_in[1];
    float* out = (float*)d_out;

    Scratch* sp = nullptr;
    cudaGetSymbolAddress((void**)&sp, S);
    float* Cxx = sp->Cxx; float* Cyy = sp->Cyy;
    float* C   = sp->C;   float* CT  = sp->CT;
    float* xt  = sp->xt;  float* yt  = sp->yt;
    float* sqx = sp->sqx; float* sqy = sp->sqy;
    float* f0 = sp->f[0]; float* f1 = sp->f[1];
    float* g0 = sp->g[0]; float* g1 = sp->g[1];
    float* fin = (float*)sp->fin;

    for (int b = 0; b < 4; b++) {
        const float* xb = x + (size_t)b * 64 * NP;
        const float* yb = y + (size_t)b * 64 * NP;
        // cost matrices first (also puts sym_phase at global launch index 5
        // so ncu -s 5 -c 1 profiles a phase kernel)
        prep_kernel<<<16, 256>>>(xb, yb, xt, yt, sqx, sqy);
        cost_kernel<<<dim3(32, 32), 256>>>(xt, xt, sqx, sqx, Cxx);
        cost_kernel<<<dim3(32, 32), 256>>>(yt, yt, sqy, sqy, Cyy);
        cost_kernel<<<dim3(32, 32), 256>>>(xt, yt, sqx, sqy, C);
        transpose_kernel<<<dim3(128, 128), dim3(32, 8)>>>(C, CT);

        sym_phase_kernel<<<NBLK, 512>>>(Cxx, f0, f1, fin + 0 * NP);
        sym_phase_kernel<<<NBLK, 512>>>(Cyy, f0, f1, fin + 1 * NP);
        xy_phase_kernel<<<NBLK, 512>>>(C, CT, f0, f1, g0, g1,
                                       fin + 2 * NP, fin + 3 * NP);

        loss_reduce<<<1, 256>>>(fin, out, b == 0 ? 1 : 0);
    }
}

// round 8
// speedup vs baseline: 1.3122x; 1.0132x over previous
#include <cuda_runtime.h>
#include <math.h>

#define NP 4096
#define NBLK 296
#define NEG_LOGN (-8.317766166719343f)   /* -log(4096) */
#define LOG2E 1.4426950408889634f
#define LN2   0.6931471805599453f

struct __align__(16) Scratch {
    float Cxx[(size_t)NP * NP];    // 64 MB
    float Cyy[(size_t)NP * NP];    // 64 MB
    float C  [(size_t)NP * NP];    // 64 MB (xy)
    float CT [(size_t)NP * NP];    // 64 MB (xy transposed)
    float xt[NP * 64], yt[NP * 64];
    float sqx[NP], sqy[NP];
    float f[2][NP], g[2][NP];      // ping-pong potentials
    float fin[4][NP];              // faa_f, gbb_f, fba_f, gab_f
};
__device__ Scratch S;

// ---------------------------------------------------------------------------
// software grid barrier (all NBLK blocks co-resident: 2 blocks / SM exactly;
// __launch_bounds__(512,2) on the phase kernel enforces the reg budget)
// ---------------------------------------------------------------------------
__device__ unsigned g_cnt;
__device__ unsigned g_gen;

__device__ __forceinline__ void gsync() {
    __threadfence();
    __syncthreads();
    if (threadIdx.x == 0) {
        volatile unsigned* vg = &g_gen;
        unsigned my = *vg;
        if (atomicAdd(&g_cnt, 1u) == NBLK - 1u) {
            g_cnt = 0u;
            __threadfence();
            *vg = my + 1u;
        } else {
            while (*vg == my) { __nanosleep(32); }
        }
    }
    __syncthreads();
}

// ---------------------------------------------------------------------------
// prep: transpose x[b] (C-major) -> xt (point-major) + squared norms
// ---------------------------------------------------------------------------
__global__ void prep_kernel(const float* __restrict__ x, const float* __restrict__ y,
                            float* __restrict__ xt, float* __restrict__ yt,
                            float* __restrict__ sqx, float* __restrict__ sqy) {
    int p = blockIdx.x * blockDim.x + threadIdx.x;
    float sx = 0.f, sy = 0.f;
    #pragma unroll 8
    for (int c = 0; c < 64; c++) {
        float vx = x[c * NP + p];
        float vy = y[c * NP + p];
        xt[p * 64 + c] = vx;
        yt[p * 64 + c] = vy;
        sx = fmaf(vx, vx, sx);
        sy = fmaf(vy, vy, sy);
    }
    sqx[p] = sx; sqy[p] = sy;
}

// ---------------------------------------------------------------------------
// cost: C[i][j] = 0.5*(|a_i|^2 + |b_j|^2 - 2 a_i.b_j)
// ---------------------------------------------------------------------------
__global__ void cost_kernel(const float* __restrict__ A, const float* __restrict__ Bm,
                            const float* __restrict__ sqa, const float* __restrict__ sqb,
                            float* __restrict__ C) {
    __shared__ float As[16 * 128];
    __shared__ float Bs[16 * 128];
    int tid = threadIdx.x;
    int tx = tid & 15, ty = tid >> 4;
    int i0 = blockIdx.y * 128, j0 = blockIdx.x * 128;

    float acc[8][8];
    #pragma unroll
    for (int r = 0; r < 8; r++)
        #pragma unroll
        for (int c = 0; c < 8; c++) acc[r][c] = 0.f;

    for (int c0 = 0; c0 < 64; c0 += 16) {
        #pragma unroll
        for (int n = 0; n < 2; n++) {
            int idx = tid + n * 256;
            int r = idx >> 2, q = idx & 3;
            float4 va = *(const float4*)&A[(size_t)(i0 + r) * 64 + c0 + q * 4];
            As[(q * 4 + 0) * 128 + r] = va.x;
            As[(q * 4 + 1) * 128 + r] = va.y;
            As[(q * 4 + 2) * 128 + r] = va.z;
            As[(q * 4 + 3) * 128 + r] = va.w;
            float4 vb = *(const float4*)&Bm[(size_t)(j0 + r) * 64 + c0 + q * 4];
            Bs[(q * 4 + 0) * 128 + r] = vb.x;
            Bs[(q * 4 + 1) * 128 + r] = vb.y;
            Bs[(q * 4 + 2) * 128 + r] = vb.z;
            Bs[(q * 4 + 3) * 128 + r] = vb.w;
        }
        __syncthreads();
        #pragma unroll
        for (int k = 0; k < 16; k++) {
            float a[8], bb[8];
            *(float4*)&a[0]  = *(const float4*)&As[k * 128 + ty * 8];
            *(float4*)&a[4]  = *(const float4*)&As[k * 128 + ty * 8 + 4];
            *(float4*)&bb[0] = *(const float4*)&Bs[k * 128 + tx * 8];
            *(float4*)&bb[4] = *(const float4*)&Bs[k * 128 + tx * 8 + 4];
            #pragma unroll
            for (int r = 0; r < 8; r++)
                #pragma unroll
                for (int c = 0; c < 8; c++)
                    acc[r][c] = fmaf(a[r], bb[c], acc[r][c]);
        }
        __syncthreads();
    }

    float sj[8];
    #pragma unroll
    for (int c = 0; c < 8; c++) sj[c] = sqb[j0 + tx * 8 + c];

    #pragma unroll
    for (int r = 0; r < 8; r++) {
        int i = i0 + ty * 8 + r;
        float si = sqa[i];
        float o[8];
        #pragma unroll
        for (int c = 0; c < 8; c++)
            o[c] = 0.5f * (si + sj[c] - 2.f * acc[r][c]);
        float* dst = &C[(size_t)i * NP + j0 + tx * 8];
        *(float4*)&dst[0] = *(float4*)&o[0];
        *(float4*)&dst[4] = *(float4*)&o[4];
    }
}

// ---------------------------------------------------------------------------
// transpose C -> CT (32x32 smem tiles)
// ---------------------------------------------------------------------------
__global__ void transpose_kernel(const float* __restrict__ A, float* __restrict__ B) {
    __shared__ float t[32][33];
    int x = blockIdx.x * 32 + threadIdx.x;
    int y = blockIdx.y * 32 + threadIdx.y;
    #pragma unroll
    for (int j = 0; j < 32; j += 8)
        t[threadIdx.y + j][threadIdx.x] = A[(size_t)(y + j) * NP + x];
    __syncthreads();
    x = blockIdx.y * 32 + threadIdx.x;
    y = blockIdx.x * 32 + threadIdx.y;
    #pragma unroll
    for (int j = 0; j < 32; j += 8)
        B[(size_t)(y + j) * NP + x] = t[threadIdx.x][threadIdx.y + j];
}

// ---------------------------------------------------------------------------
// dual-stream chunked exact online-LSE (base-2).
// Stream A: default cache policy (L2-resident matrix).
// Stream B: __ldcs streaming (evict-first; protects A's residency).
// ---------------------------------------------------------------------------
__device__ __forceinline__ void chunk16(const float4* c, const float4* h,
                                        float k, float& m, float& s) {
    float v[16];
    #pragma unroll
    for (int q = 0; q < 4; q++) {
        v[q*4+0] = fmaf(c[q].x, k, h[q].x);
        v[q*4+1] = fmaf(c[q].y, k, h[q].y);
        v[q*4+2] = fmaf(c[q].z, k, h[q].z);
        v[q*4+3] = fmaf(c[q].w, k, h[q].w);
    }
    float cm = v[0];
    #pragma unroll
    for (int t = 1; t < 16; t++) cm = fmaxf(cm, v[t]);
    float cs = 0.f;
    #pragma unroll
    for (int t = 0; t < 16; t++) cs += exp2f(v[t] - cm);
    float nm = fmaxf(m, cm);
    s = s * exp2f(m - nm) + cs * exp2f(cm - nm);
    m = nm;
}

__device__ __forceinline__ float2 row_lse2_dual(
        const float4* __restrict__ CrA, const float4* __restrict__ CrB,
        const float4* __restrict__ HA,  const float4* __restrict__ HB,
        float k, int lane) {
    float mA = -INFINITY, sA = 0.f;
    float mB = -INFINITY, sB = 0.f;
    #pragma unroll
    for (int seg = 0; seg < 8; seg++) {
        int b = seg * 128 + lane;
        float4 a[4], bb[4];
        a[0]  = CrA[b];      a[1]  = CrA[b + 32];
        a[2]  = CrA[b + 64]; a[3]  = CrA[b + 96];
        bb[0] = __ldcs(CrB + b);      bb[1] = __ldcs(CrB + b + 32);
        bb[2] = __ldcs(CrB + b + 64); bb[3] = __ldcs(CrB + b + 96);
        float4 ha[4], hb4[4];
        ha[0]  = HA[b];      ha[1]  = HA[b + 32];
        ha[2]  = HA[b + 64]; ha[3]  = HA[b + 96];
        hb4[0] = HB[b];      hb4[1] = HB[b + 32];
        hb4[2] = HB[b + 64]; hb4[3] = HB[b + 96];
        chunk16(a,  ha,  k, mA, sA);
        chunk16(bb, hb4, k, mB, sB);
    }
    #pragma unroll
    for (int off = 16; off; off >>= 1) {
        float om = __shfl_xor_sync(0xffffffffu, mA, off);
        float os = __shfl_xor_sync(0xffffffffu, sA, off);
        float nm = fmaxf(mA, om);
        sA = sA * exp2f(mA - nm) + os * exp2f(om - nm);
        mA = nm;
        float om2 = __shfl_xor_sync(0xffffffffu, mB, off);
        float os2 = __shfl_xor_sync(0xffffffffu, sB, off);
        float nm2 = fmaxf(mB, om2);
        sB = sB * exp2f(mB - nm2) + os2 * exp2f(om2 - nm2);
        mB = nm2;
    }
    return make_float2(mA + log2f(sA), mB + log2f(sB));
}

__device__ __forceinline__ void init_eps(float* sh_eps, int tid) {
    if (tid < 56) {
        double e = (tid < 55)
            ? exp(5.545177444479562 - 0.21072103131565253 * (double)tid)
            : 0.0025;
        sh_eps[tid] = (float)e;
    }
}

// h-prefill: sh[j] = (pot[j]/eps + NEG_LOGN) * LOG2E, float4-wide
__device__ __forceinline__ void fill_bias(float* sh, const float* pot,
                                          float inv_e, int tid) {
    const float4* p4 = (const float4*)pot;
    float4* s4 = (float4*)sh;
    #pragma unroll
    for (int q = 0; q < 2; q++) {
        int j = tid + q * 512;
        float4 v = __ldcg(p4 + j);
        float4 o;
        o.x = fmaf(v.x, inv_e, NEG_LOGN) * LOG2E;
        o.y = fmaf(v.y, inv_e, NEG_LOGN) * LOG2E;
        o.z = fmaf(v.z, inv_e, NEG_LOGN) * LOG2E;
        o.w = fmaf(v.w, inv_e, NEG_LOGN) * LOG2E;
        s4[j] = o;
    }
}

// ---------------------------------------------------------------------------
// dual annealing phase: two independent softmin streams per iteration.
//   stream A: row r of CA, bias from biasA[cur], update updA  (L2-resident)
//   stream B: row r of CB, bias from biasB[cur], update updB  (streamed)
// xy:  CA=C,  CB=CT,  biasA=g(ping),  updA=f(ping), biasB=f, updB=g (cross)
// sym: CA=Cxx,CB=Cyy, biasA=updA=f,   biasB=updB=g            (self)
// ---------------------------------------------------------------------------
__global__ void __launch_bounds__(512, 2) dual_phase_kernel(
        const float* __restrict__ CA, const float* __restrict__ CB,
        float* __restrict__ bA0, float* __restrict__ bA1,
        float* __restrict__ uA0, float* __restrict__ uA1,
        float* __restrict__ bB0, float* __restrict__ bB1,
        float* __restrict__ uB0, float* __restrict__ uB1,
        float* __restrict__ outA, float* __restrict__ outB) {
    __shared__ __align__(16) float shA[NP];
    __shared__ __align__(16) float shB[NP];
    __shared__ float sh_eps[56];
    int tid = threadIdx.x, lane = tid & 31, warp = tid >> 5;
    int row = warp * NBLK + (int)blockIdx.x;
    bool active = row < NP;
    int prow = active ? row : 0;
    init_eps(sh_eps, tid);
    const float4* CrA = (const float4*)(CA + (size_t)prow * NP);
    const float4* CrB = (const float4*)(CB + (size_t)prow * NP);
    float* bA[2] = { bA0, bA1 };
    float* uA[2] = { uA0, uA1 };
    float* bB[2] = { bB0, bB1 };
    float* uB[2] = { uB0, uB1 };
    int cur = 0;
    __syncthreads();                               // sh_eps ready

    for (int t = 0; t <= 57; t++) {
        int ke = (t == 0) ? 0 : (t == 57 ? 55 : t - 1);
        float e = sh_eps[ke];
        float inv_e = 1.f / e;
        float k = -inv_e * LOG2E;

        if (t == 0) {
            for (int j = tid; j < NP; j += 512) {
                shA[j] = NEG_LOGN * LOG2E;
                shB[j] = NEG_LOGN * LOG2E;
            }
        } else {
            fill_bias(shA, bA[cur], inv_e, tid);
            fill_bias(shB, bB[cur], inv_e, tid);
        }
        __syncthreads();

        float2 ls = row_lse2_dual(CrA, CrB, (const float4*)shA,
                                  (const float4*)shB, k, lane);

        if (lane == 0 && active) {
            float vA = -e * LN2 * ls.x;
            float vB = -e * LN2 * ls.y;
            if (t == 57) {
                outA[row] = vA;
                outB[row] = vB;
            } else if (t == 0) {
                __stcg(&uA[1][row], vA);
                __stcg(&uB[1][row], vB);
            } else {
                __stcg(&uA[cur ^ 1][row],
                       0.5f * __ldcg(&uA[cur][row]) + 0.5f * vA);
                __stcg(&uB[cur ^ 1][row],
                       0.5f * __ldcg(&uB[cur][row]) + 0.5f * vB);
            }
        }
        if (t == 0) cur = 1; else if (t < 57) cur ^= 1;
        if (t < 57) gsync();
    }
}

// ---------------------------------------------------------------------------
// loss: out (+)= [ mean(fba_f - faa_f) + mean(gab_f - gbb_f) ] / B
// ---------------------------------------------------------------------------
__global__ void loss_reduce(const float* __restrict__ fin, float* __restrict__ out, int first) {
    __shared__ float red[256];
    int tid = threadIdx.x;
    float a = 0.f;
    for (int j = tid; j < NP; j += 256)
        a += (fin[2 * NP + j] - fin[0 * NP + j]) + (fin[3 * NP + j] - fin[1 * NP + j]);
    red[tid] = a;
    __syncthreads();
    for (int sft = 128; sft; sft >>= 1) {
        if (tid < sft) red[tid] += red[tid + sft];
        __syncthreads();
    }
    if (tid == 0) {
        float v = red[0] * (1.0f / NP) * 0.25f;
        if (first) *out = v; else *out += v;
    }
}

// ---------------------------------------------------------------------------
extern "C" void kernel_launch(void* const* d_in, const int* in_sizes, int n_in,
                              void* d_out, int out_size) {
    (void)in_sizes; (void)n_in; (void)out_size;
    const float* x = (const float*)d_in[0];
    const float* y = (const float*)d_in[1];
    float* out = (float*)d_out;

    Scratch* sp = nullptr;
    cudaGetSymbolAddress((void**)&sp, S);
    float* Cxx = sp->Cxx; float* Cyy = sp->Cyy;
    float* C   = sp->C;   float* CT  = sp->CT;
    float* xt  = sp->xt;  float* yt  = sp->yt;
    float* sqx = sp->sqx; float* sqy = sp->sqy;
    float* f0 = sp->f[0]; float* f1 = sp->f[1];
    float* g0 = sp->g[0]; float* g1 = sp->g[1];
    float* fin = (float*)sp->fin;

    for (int b = 0; b < 4; b++) {
        const float* xb = x + (size_t)b * 64 * NP;
        const float* yb = y + (size_t)b * 64 * NP;
        prep_kernel<<<16, 256>>>(xb, yb, xt, yt, sqx, sqy);
        cost_kernel<<<dim3(32, 32), 256>>>(xt, xt, sqx, sqx, Cxx);
        cost_kernel<<<dim3(32, 32), 256>>>(yt, yt, sqy, sqy, Cyy);
        cost_kernel<<<dim3(32, 32), 256>>>(xt, yt, sqx, sqy, C);
        transpose_kernel<<<dim3(128, 128), dim3(32, 8)>>>(C, CT);

        // fused xx+yy phase: A=Cxx->f_aa (self-coupled), B=Cyy->g_bb (self)
        dual_phase_kernel<<<NBLK, 512>>>(Cxx, Cyy,
                                         f0, f1, f0, f1,
                                         g0, g1, g0, g1,
                                         fin + 0 * NP, fin + 1 * NP);
        // xy phase: A=C (bias g, update f), B=CT (bias f, update g)
        dual_phase_kernel<<<NBLK, 512>>>(C, CT,
                                         g0, g1, f0, f1,
                                         f0, f1, g0, g1,
                                         fin + 2 * NP, fin + 3 * NP);

        loss_reduce<<<1, 256>>>(fin, out, b == 0 ? 1 : 0);
    }
}